// round 5
// baseline (speedup 1.0000x reference)
#include <cuda_runtime.h>
#include <math.h>

#define NEG_SLOPE 0.2f
static const int NN  = 50000;   // nodes
static const int NE  = 800000;  // real edges
static const int ET  = 850000;  // edges + self loops
static const int NG  = 64;      // graphs
static const int FIN = 500;
static const int F1  = 256;     // H1*C1
static const int H1N = 4;
static const int C1  = 64;
static const int C2  = 64;

// ---- scratch (static device allocations only, per harness rules) ----
// 16B alignment: these are touched with 128-bit vector loads/stores.
__device__ __align__(16) float g_h1  [NN * F1];    // layer1 features h = x@W1
__device__ __align__(16) float g_out1[NN * F1];    // layer1 aggregated output
__device__ __align__(16) float g_h2  [NN * C2];    // layer2 features
__device__ __align__(16) float g_out2[NN * C2];    // layer2 aggregated output
__device__ __align__(16) float g_als1[NN * H1N];
__device__ __align__(16) float g_ald1[NN * H1N];
__device__ __align__(16) int   g_m1  [NN * H1N];   // ordered-int max
__device__ __align__(16) float g_s1  [NN * H1N];
__device__ __align__(16) float g_e1  [ET * H1N];   // logits, then exp()
__device__ float g_als2[NN];
__device__ float g_ald2[NN];
__device__ int   g_m2  [NN];
__device__ float g_s2  [NN];
__device__ float g_e2  [ET];
__device__ float g_pool[NG * C2];
__device__ float g_cnt [NG];

// ---- helpers ----
__device__ __forceinline__ int f2o(float f) {
    int i = __float_as_int(f);
    return i >= 0 ? i : i ^ 0x7FFFFFFF;   // monotone float->int map
}
__device__ __forceinline__ float o2f(int i) {
    return __int_as_float(i >= 0 ? i : i ^ 0x7FFFFFFF);
}
__device__ __forceinline__ void redAdd4(float* p, float a, float b, float c, float d) {
    asm volatile("red.global.add.v4.f32 [%0], {%1,%2,%3,%4};"
                 :: "l"(p), "f"(a), "f"(b), "f"(c), "f"(d) : "memory");
}
__device__ __forceinline__ float lrelu(float v) {
    return v > 0.f ? v : NEG_SLOPE * v;
}

// ---- init: zero accumulators, set maxima to -inf ----
__global__ void k_init() {
    int NEG = f2o(__int_as_float(0xff800000));   // -inf, monotone-mapped
    long long i = (long long)blockIdx.x * blockDim.x + threadIdx.x;
    long long stride = (long long)gridDim.x * blockDim.x;
    for (long long t = i; t < (long long)NN * F1; t += stride) g_out1[t] = 0.f;
    for (long long t = i; t < (long long)NN * C2; t += stride) g_out2[t] = 0.f;
    for (long long t = i; t < (long long)NN * H1N; t += stride) { g_s1[t] = 0.f; g_m1[t] = NEG; }
    for (long long t = i; t < NN; t += stride) { g_s2[t] = 0.f; g_m2[t] = NEG; }
    if (i < NG * C2) g_pool[i] = 0.f;
    if (i < NG) g_cnt[i] = 0.f;
}

// ---- GEMM1: g_h1[50000,256] = X[50000,500] @ W1[500,256] ----
// 128x128 block tile, BK=4 (500 = 125*4 exactly), 8x8 per-thread micro tile.
__global__ __launch_bounds__(256) void k_gemm1(const float* __restrict__ X,
                                               const float* __restrict__ W) {
    __shared__ float As[4][128];
    __shared__ float Bs[4][128];
    const int tid = threadIdx.x;
    const int tx = tid & 15;
    const int ty = tid >> 4;
    const int rowBase = blockIdx.y * 128;
    const int colBase = blockIdx.x * 128;
    float acc[8][8];
#pragma unroll
    for (int i = 0; i < 8; i++)
#pragma unroll
        for (int j = 0; j < 8; j++) acc[i][j] = 0.f;

    for (int k0 = 0; k0 < FIN; k0 += 4) {
        if (tid < 128) {
            // A: 128 rows x 4 k each, one float4 per thread (row stride 500 floats
            // = 2000B, 16B-aligned, k0 multiple of 4 -> aligned vector load)
            int r = tid;
            int grow = rowBase + r;
            float4 v = make_float4(0.f, 0.f, 0.f, 0.f);
            if (grow < NN) v = *(const float4*)(X + (long long)grow * FIN + k0);
            As[0][r] = v.x; As[1][r] = v.y; As[2][r] = v.z; As[3][r] = v.w;
        } else {
            // B: 4 rows x 128 cols = 128 float4
            int idx = tid - 128;
            int kk = idx >> 5, c = (idx & 31) * 4;
            *(float4*)&Bs[kk][c] = *(const float4*)(W + (k0 + kk) * F1 + colBase + c);
        }
        __syncthreads();
#pragma unroll
        for (int kk = 0; kk < 4; kk++) {
            float4 a0 = *(const float4*)&As[kk][ty * 8];
            float4 a1 = *(const float4*)&As[kk][ty * 8 + 4];
            float4 b0 = *(const float4*)&Bs[kk][tx * 8];
            float4 b1 = *(const float4*)&Bs[kk][tx * 8 + 4];
            float ra[8] = {a0.x, a0.y, a0.z, a0.w, a1.x, a1.y, a1.z, a1.w};
            float rb[8] = {b0.x, b0.y, b0.z, b0.w, b1.x, b1.y, b1.z, b1.w};
#pragma unroll
            for (int i = 0; i < 8; i++)
#pragma unroll
                for (int j = 0; j < 8; j++) acc[i][j] = fmaf(ra[i], rb[j], acc[i][j]);
        }
        __syncthreads();
    }
#pragma unroll
    for (int i = 0; i < 8; i++) {
        int row = rowBase + ty * 8 + i;
        if (row < NN) {
            float* op = g_h1 + (long long)row * F1 + colBase + tx * 8;
            *(float4*)op       = make_float4(acc[i][0], acc[i][1], acc[i][2], acc[i][3]);
            *(float4*)(op + 4) = make_float4(acc[i][4], acc[i][5], acc[i][6], acc[i][7]);
        }
    }
}

// ---- per-node attention dots layer1: warp per (node, head) ----
__global__ void k_att1(const float* __restrict__ a_src, const float* __restrict__ a_dst) {
    int warp = (blockIdx.x * blockDim.x + threadIdx.x) >> 5;
    int lane = threadIdx.x & 31;
    int n = warp >> 2;
    int h = warp & 3;
    if (n >= NN) return;
    const float* hp = g_h1 + (long long)n * F1 + h * C1;
    float v0 = hp[lane], v1 = hp[lane + 32];
    float s = v0 * __ldg(a_src + h * C1 + lane) + v1 * __ldg(a_src + h * C1 + lane + 32);
    float d = v0 * __ldg(a_dst + h * C1 + lane) + v1 * __ldg(a_dst + h * C1 + lane + 32);
#pragma unroll
    for (int o = 16; o; o >>= 1) {
        s += __shfl_down_sync(0xFFFFFFFFu, s, o);
        d += __shfl_down_sync(0xFFFFFFFFu, d, o);
    }
    if (lane == 0) { g_als1[n * H1N + h] = s; g_ald1[n * H1N + h] = d; }
}

// ---- edge logits + segment max, layer1 ----
__global__ void k_edge_max1(const int* __restrict__ src, const int* __restrict__ dst) {
    int e = blockIdx.x * blockDim.x + threadIdx.x;
    if (e >= ET) return;
    int s, d;
    if (e < NE) { s = src[e]; d = dst[e]; }
    else        { s = d = e - NE; }
    float4 as = *(const float4*)(g_als1 + s * 4);
    float4 ad = *(const float4*)(g_ald1 + d * 4);
    float v0 = lrelu(as.x + ad.x);
    float v1 = lrelu(as.y + ad.y);
    float v2 = lrelu(as.z + ad.z);
    float v3 = lrelu(as.w + ad.w);
    *(float4*)(g_e1 + (long long)e * 4) = make_float4(v0, v1, v2, v3);
    atomicMax(&g_m1[d * 4 + 0], f2o(v0));
    atomicMax(&g_m1[d * 4 + 1], f2o(v1));
    atomicMax(&g_m1[d * 4 + 2], f2o(v2));
    atomicMax(&g_m1[d * 4 + 3], f2o(v3));
}

// ---- exp + segment sum, layer1 ----
__global__ void k_edge_sum1(const int* __restrict__ src, const int* __restrict__ dst) {
    int e = blockIdx.x * blockDim.x + threadIdx.x;
    if (e >= ET) return;
    int d;
    if (e < NE) d = dst[e]; else d = e - NE;
    float4 ev = *(const float4*)(g_e1 + (long long)e * 4);
    int4 mi = *(const int4*)(g_m1 + d * 4);
    float x0 = expf(ev.x - o2f(mi.x));
    float x1 = expf(ev.y - o2f(mi.y));
    float x2 = expf(ev.z - o2f(mi.z));
    float x3 = expf(ev.w - o2f(mi.w));
    *(float4*)(g_e1 + (long long)e * 4) = make_float4(x0, x1, x2, x3);
    redAdd4(g_s1 + d * 4, x0, x1, x2, x3);
}

// ---- aggregation layer1: 64 threads per edge, float4 reduce-add ----
__global__ __launch_bounds__(256) void k_agg1(const int* __restrict__ src,
                                              const int* __restrict__ dst) {
    int t = threadIdx.x;
    int e = blockIdx.x * 4 + (t >> 6);
    if (e >= ET) return;
    int s, d;
    if (e < NE) { s = src[e]; d = dst[e]; }
    else        { s = d = e - NE; }
    int col = (t & 63) * 4;
    int h = col >> 6;
    float alpha = g_e1[(long long)e * 4 + h] / (g_s1[d * 4 + h] + 1e-16f);
    float4 hv = *(const float4*)(g_h1 + (long long)s * F1 + col);
    redAdd4(g_out1 + (long long)d * F1 + col,
            hv.x * alpha, hv.y * alpha, hv.z * alpha, hv.w * alpha);
}

// ---- GEMM2: g_h2[50000,64] = relu(g_out1 + b1) @ W2[256,64] (bias/relu fused) ----
__global__ __launch_bounds__(256) void k_gemm2(const float* __restrict__ W2,
                                               const float* __restrict__ b1) {
    __shared__ float As[16][64];
    __shared__ float Bs[16][64];
    int tid = threadIdx.x;
    int tx = tid & 15, ty = tid >> 4;
    int rowBase = blockIdx.x * 64;
    float acc[4][4];
#pragma unroll
    for (int i = 0; i < 4; i++)
#pragma unroll
        for (int j = 0; j < 4; j++) acc[i][j] = 0.f;

    for (int k0 = 0; k0 < 256; k0 += 16) {
        {
            int r = tid >> 2;
            int kk = (tid & 3) * 4;
            int grow = rowBase + r;
            float4 v = make_float4(0.f, 0.f, 0.f, 0.f);
            if (grow < NN) {
                float4 o = *(const float4*)(g_out1 + (long long)grow * F1 + k0 + kk);
                float4 bb = *(const float4*)(b1 + k0 + kk);
                v.x = fmaxf(o.x + bb.x, 0.f);
                v.y = fmaxf(o.y + bb.y, 0.f);
                v.z = fmaxf(o.z + bb.z, 0.f);
                v.w = fmaxf(o.w + bb.w, 0.f);
            }
            As[kk][r] = v.x; As[kk + 1][r] = v.y; As[kk + 2][r] = v.z; As[kk + 3][r] = v.w;
        }
        {
            int kk = tid >> 4, c = (tid & 15) * 4;
            *(float4*)&Bs[kk][c] = *(const float4*)(W2 + (k0 + kk) * 64 + c);
        }
        __syncthreads();
#pragma unroll
        for (int kk = 0; kk < 16; kk++) {
            float4 a = *(const float4*)&As[kk][ty * 4];
            float4 b = *(const float4*)&Bs[kk][tx * 4];
            float ra[4] = {a.x, a.y, a.z, a.w};
            float rb[4] = {b.x, b.y, b.z, b.w};
#pragma unroll
            for (int i = 0; i < 4; i++)
#pragma unroll
                for (int j = 0; j < 4; j++) acc[i][j] = fmaf(ra[i], rb[j], acc[i][j]);
        }
        __syncthreads();
    }
#pragma unroll
    for (int i = 0; i < 4; i++) {
        int row = rowBase + ty * 4 + i;
        if (row < NN)
            *(float4*)(g_h2 + (long long)row * 64 + tx * 4) =
                make_float4(acc[i][0], acc[i][1], acc[i][2], acc[i][3]);
    }
}

// ---- per-node attention dots layer2 (H=1): warp per node ----
__global__ void k_att2(const float* __restrict__ a_src, const float* __restrict__ a_dst) {
    int n = (blockIdx.x * blockDim.x + threadIdx.x) >> 5;
    int lane = threadIdx.x & 31;
    if (n >= NN) return;
    const float* hp = g_h2 + (long long)n * 64;
    float v0 = hp[lane], v1 = hp[lane + 32];
    float s = v0 * __ldg(a_src + lane) + v1 * __ldg(a_src + lane + 32);
    float d = v0 * __ldg(a_dst + lane) + v1 * __ldg(a_dst + lane + 32);
#pragma unroll
    for (int o = 16; o; o >>= 1) {
        s += __shfl_down_sync(0xFFFFFFFFu, s, o);
        d += __shfl_down_sync(0xFFFFFFFFu, d, o);
    }
    if (lane == 0) { g_als2[n] = s; g_ald2[n] = d; }
}

__global__ void k_edge_max2(const int* __restrict__ src, const int* __restrict__ dst) {
    int e = blockIdx.x * blockDim.x + threadIdx.x;
    if (e >= ET) return;
    int s, d;
    if (e < NE) { s = src[e]; d = dst[e]; }
    else        { s = d = e - NE; }
    float v = lrelu(g_als2[s] + g_ald2[d]);
    g_e2[e] = v;
    atomicMax(&g_m2[d], f2o(v));
}

__global__ void k_edge_sum2(const int* __restrict__ src, const int* __restrict__ dst) {
    int e = blockIdx.x * blockDim.x + threadIdx.x;
    if (e >= ET) return;
    int d;
    if (e < NE) d = dst[e]; else d = e - NE;
    float x = expf(g_e2[e] - o2f(g_m2[d]));
    g_e2[e] = x;
    atomicAdd(&g_s2[d], x);
}

// ---- aggregation layer2: 16 threads per edge, float4 reduce-add over 64 cols ----
__global__ __launch_bounds__(256) void k_agg2(const int* __restrict__ src,
                                              const int* __restrict__ dst) {
    int t = threadIdx.x;
    int e = blockIdx.x * 16 + (t >> 4);
    if (e >= ET) return;
    int s, d;
    if (e < NE) { s = src[e]; d = dst[e]; }
    else        { s = d = e - NE; }
    int col = (t & 15) * 4;
    float alpha = g_e2[e] / (g_s2[d] + 1e-16f);
    float4 hv = *(const float4*)(g_h2 + (long long)s * 64 + col);
    redAdd4(g_out2 + (long long)d * 64 + col,
            hv.x * alpha, hv.y * alpha, hv.z * alpha, hv.w * alpha);
}

// ---- epilogue layer2 + mean pool: warp per node ----
__global__ void k_pool(const int* __restrict__ batch, const float* __restrict__ b2) {
    int n = (blockIdx.x * blockDim.x + threadIdx.x) >> 5;
    int lane = threadIdx.x & 31;
    if (n >= NN) return;
    int b = batch[n];
    float v0 = fmaxf(g_out2[(long long)n * 64 + lane]      + __ldg(b2 + lane),      0.f);
    float v1 = fmaxf(g_out2[(long long)n * 64 + lane + 32] + __ldg(b2 + lane + 32), 0.f);
    atomicAdd(&g_pool[b * 64 + lane],      v0);
    atomicAdd(&g_pool[b * 64 + lane + 32], v1);
    if (lane == 0) atomicAdd(&g_cnt[b], 1.f);
}

// ---- final: out[64,2] = (pool/cnt) @ Wl + bl ----
__global__ void k_final(const float* __restrict__ Wl, const float* __restrict__ bl,
                        float* __restrict__ out) {
    int t = threadIdx.x;
    if (t >= NG * 2) return;
    int g = t >> 1, j = t & 1;
    float c = fmaxf(g_cnt[g], 1.f);
    float acc = 0.f;
#pragma unroll
    for (int k = 0; k < 64; k++) acc += (g_pool[g * 64 + k] / c) * Wl[k * 2 + j];
    out[g * 2 + j] = acc + bl[j];
}

extern "C" void kernel_launch(void* const* d_in, const int* in_sizes, int n_in,
                              void* d_out, int out_size) {
    const float* x     = (const float*)d_in[0];
    const int*   ei    = (const int*)d_in[1];      // int32 (JAX x64 disabled)
    const int*   batch = (const int*)d_in[2];
    const float* W1    = (const float*)d_in[3];
    const float* as1   = (const float*)d_in[4];
    const float* ad1   = (const float*)d_in[5];
    const float* b1    = (const float*)d_in[6];
    const float* W2    = (const float*)d_in[7];
    const float* as2   = (const float*)d_in[8];
    const float* ad2   = (const float*)d_in[9];
    const float* b2    = (const float*)d_in[10];
    const float* Wl    = (const float*)d_in[11];
    const float* bl    = (const float*)d_in[12];
    float*       out   = (float*)d_out;
    const int* src = ei;
    const int* dst = ei + NE;

    int eb = (ET + 255) / 256;

    k_init<<<4096, 256>>>();
    {
        dim3 g(2, (NN + 127) / 128);
        k_gemm1<<<g, 256>>>(x, W1);
    }
    k_att1<<<(NN * H1N + 7) / 8, 256>>>(as1, ad1);
    k_edge_max1<<<eb, 256>>>(src, dst);
    k_edge_sum1<<<eb, 256>>>(src, dst);
    k_agg1<<<(ET + 3) / 4, 256>>>(src, dst);
    k_gemm2<<<(NN + 63) / 64, 256>>>(W2, b1);
    k_att2<<<(NN + 7) / 8, 256>>>(as2, ad2);
    k_edge_max2<<<eb, 256>>>(src, dst);
    k_edge_sum2<<<eb, 256>>>(src, dst);
    k_agg2<<<(ET + 15) / 16, 256>>>(src, dst);
    k_pool<<<(NN + 7) / 8, 256>>>(batch, b2);
    k_final<<<1, 128>>>(Wl, bl, out);
}

// round 7
// speedup vs baseline: 1.2885x; 1.2885x over previous
#include <cuda_runtime.h>
#include <math.h>

#define NEG_SLOPE 0.2f
static const int NN  = 50000;   // nodes
static const int NE  = 800000;  // real edges
static const int ET  = 850000;  // edges + self loops
static const int NG  = 64;      // graphs
static const int FIN = 500;
static const int F1  = 256;     // H1*C1
static const int H1N = 4;
static const int C2  = 64;

// ---- scratch (static device allocations only, per harness rules) ----
__device__ __align__(16) float g_h1  [NN * F1];    // layer1 features h = x@W1
__device__ __align__(16) float g_out1[NN * F1];    // layer1 unnormalized aggregate
__device__ __align__(16) float g_h2  [NN * C2];    // layer2 features
__device__ __align__(16) float g_out2[NN * C2];    // layer2 unnormalized aggregate
__device__ __align__(16) float g_als1[NN * H1N];
__device__ __align__(16) float g_ald1[NN * H1N];
__device__ __align__(16) float g_s1  [NN * H1N];   // softmax denominators (unshifted)
__device__ __align__(16) float g_e1  [ET * H1N];   // exp(logits), unnormalized
__device__ float g_als2[NN];
__device__ float g_ald2[NN];
__device__ float g_s2  [NN];
__device__ float g_e2  [ET];
__device__ float g_pool[NG * C2];
__device__ float g_cnt [NG];

// ---- helpers ----
__device__ __forceinline__ void redAdd4(float* p, float a, float b, float c, float d) {
    asm volatile("red.global.add.v4.f32 [%0], {%1,%2,%3,%4};"
                 :: "l"(p), "f"(a), "f"(b), "f"(c), "f"(d) : "memory");
}
__device__ __forceinline__ float lrelu(float v) {
    return v > 0.f ? v : NEG_SLOPE * v;
}

// ---- init: zero accumulators ----
__global__ void k_init() {
    long long i = (long long)blockIdx.x * blockDim.x + threadIdx.x;
    long long stride = (long long)gridDim.x * blockDim.x;
    for (long long t = i; t < (long long)NN * F1; t += stride) g_out1[t] = 0.f;
    for (long long t = i; t < (long long)NN * C2; t += stride) g_out2[t] = 0.f;
    for (long long t = i; t < (long long)NN * H1N; t += stride) g_s1[t] = 0.f;
    for (long long t = i; t < NN; t += stride) g_s2[t] = 0.f;
    if (i < NG * C2) g_pool[i] = 0.f;
    if (i < NG) g_cnt[i] = 0.f;
}

// ---- GEMM1: g_h1[50000,256] = X[50000,500] @ W1[500,256] ----
// 128x128 tile, BK=8 double-buffered (62 stages of 8 + 1 tail of 4 = 500),
// 8x8 per-thread micro tile, global loads overlapped with FMA.
__global__ __launch_bounds__(256) void k_gemm1(const float* __restrict__ X,
                                               const float* __restrict__ W) {
    __shared__ float As[2][8][128];
    __shared__ float Bs[2][8][128];
    const int tid = threadIdx.x;
    const int tx = tid & 15;
    const int ty = tid >> 4;
    const int rowBase = blockIdx.y * 128;
    const int colBase = blockIdx.x * 128;
    const int arow = tid >> 1, akk = (tid & 1) * 4;   // A: 128 rows x 8 k per stage
    const int brow = tid >> 5, bcol = (tid & 31) * 4; // B: 8 rows x 128 cols per stage

    float acc[8][8];
#pragma unroll
    for (int i = 0; i < 8; i++)
#pragma unroll
        for (int j = 0; j < 8; j++) acc[i][j] = 0.f;

    // preload stage 0
    {
        int grow = rowBase + arow;
        float4 v = make_float4(0.f, 0.f, 0.f, 0.f);
        if (grow < NN) v = *(const float4*)(X + (long long)grow * FIN + akk);
        As[0][akk][arow] = v.x; As[0][akk + 1][arow] = v.y;
        As[0][akk + 2][arow] = v.z; As[0][akk + 3][arow] = v.w;
        *(float4*)&Bs[0][brow][bcol] = *(const float4*)(W + brow * F1 + colBase + bcol);
    }
    __syncthreads();

    for (int it = 0; it < 62; it++) {
        const int cur = it & 1, nxt = cur ^ 1;
        const int kNext = (it + 1) * 8;
        const bool full = (it < 61);          // stage 62 is the 4-wide tail (k=496..499)
        const bool doA = full || (akk == 0);
        const bool doB = full || (brow < 4);
        float4 va = make_float4(0.f, 0.f, 0.f, 0.f), vb;
        {
            int grow = rowBase + arow;
            if (doA && grow < NN)
                va = *(const float4*)(X + (long long)grow * FIN + kNext + akk);
            if (doB)
                vb = *(const float4*)(W + (kNext + brow) * F1 + colBase + bcol);
        }
#pragma unroll
        for (int kk = 0; kk < 8; kk++) {
            float4 a0 = *(const float4*)&As[cur][kk][ty * 8];
            float4 a1 = *(const float4*)&As[cur][kk][ty * 8 + 4];
            float4 b0 = *(const float4*)&Bs[cur][kk][tx * 8];
            float4 b1 = *(const float4*)&Bs[cur][kk][tx * 8 + 4];
            float ra[8] = {a0.x, a0.y, a0.z, a0.w, a1.x, a1.y, a1.z, a1.w};
            float rb[8] = {b0.x, b0.y, b0.z, b0.w, b1.x, b1.y, b1.z, b1.w};
#pragma unroll
            for (int i = 0; i < 8; i++)
#pragma unroll
                for (int j = 0; j < 8; j++) acc[i][j] = fmaf(ra[i], rb[j], acc[i][j]);
        }
        if (doA) {
            As[nxt][akk][arow] = va.x; As[nxt][akk + 1][arow] = va.y;
            As[nxt][akk + 2][arow] = va.z; As[nxt][akk + 3][arow] = va.w;
        }
        if (doB) *(float4*)&Bs[nxt][brow][bcol] = vb;
        __syncthreads();
    }
    // tail stage (4 wide) sits in buffer 0
#pragma unroll
    for (int kk = 0; kk < 4; kk++) {
        float4 a0 = *(const float4*)&As[0][kk][ty * 8];
        float4 a1 = *(const float4*)&As[0][kk][ty * 8 + 4];
        float4 b0 = *(const float4*)&Bs[0][kk][tx * 8];
        float4 b1 = *(const float4*)&Bs[0][kk][tx * 8 + 4];
        float ra[8] = {a0.x, a0.y, a0.z, a0.w, a1.x, a1.y, a1.z, a1.w};
        float rb[8] = {b0.x, b0.y, b0.z, b0.w, b1.x, b1.y, b1.z, b1.w};
#pragma unroll
        for (int i = 0; i < 8; i++)
#pragma unroll
            for (int j = 0; j < 8; j++) acc[i][j] = fmaf(ra[i], rb[j], acc[i][j]);
    }

#pragma unroll
    for (int i = 0; i < 8; i++) {
        int row = rowBase + ty * 8 + i;
        if (row < NN) {
            float* op = g_h1 + (long long)row * F1 + colBase + tx * 8;
            *(float4*)op       = make_float4(acc[i][0], acc[i][1], acc[i][2], acc[i][3]);
            *(float4*)(op + 4) = make_float4(acc[i][4], acc[i][5], acc[i][6], acc[i][7]);
        }
    }
}

// ---- per-node attention dots layer1: warp per (node, head) ----
__global__ void k_att1(const float* __restrict__ a_src, const float* __restrict__ a_dst) {
    int warp = (blockIdx.x * blockDim.x + threadIdx.x) >> 5;
    int lane = threadIdx.x & 31;
    int n = warp >> 2;
    int h = warp & 3;
    if (n >= NN) return;
    const float* hp = g_h1 + (long long)n * F1 + h * 64;
    float v0 = hp[lane], v1 = hp[lane + 32];
    float s = v0 * __ldg(a_src + h * 64 + lane) + v1 * __ldg(a_src + h * 64 + lane + 32);
    float d = v0 * __ldg(a_dst + h * 64 + lane) + v1 * __ldg(a_dst + h * 64 + lane + 32);
#pragma unroll
    for (int o = 16; o; o >>= 1) {
        s += __shfl_down_sync(0xFFFFFFFFu, s, o);
        d += __shfl_down_sync(0xFFFFFFFFu, d, o);
    }
    if (lane == 0) { g_als1[n * H1N + h] = s; g_ald1[n * H1N + h] = d; }
}

// ---- fused logit + exp + segment sum, layer1 (softmax shift dropped:
//      exp(e)/sum(exp(e)) is mathematically identical to the shifted form) ----
__global__ void k_edge_sum1(const int* __restrict__ src, const int* __restrict__ dst) {
    int e = blockIdx.x * blockDim.x + threadIdx.x;
    if (e >= ET) return;
    int s, d;
    if (e < NE) { s = src[e]; d = dst[e]; }
    else        { s = d = e - NE; }
    float4 as = *(const float4*)(g_als1 + s * 4);
    float4 ad = *(const float4*)(g_ald1 + d * 4);
    float x0 = expf(lrelu(as.x + ad.x));
    float x1 = expf(lrelu(as.y + ad.y));
    float x2 = expf(lrelu(as.z + ad.z));
    float x3 = expf(lrelu(as.w + ad.w));
    *(float4*)(g_e1 + (long long)e * 4) = make_float4(x0, x1, x2, x3);
    redAdd4(g_s1 + d * 4, x0, x1, x2, x3);
}

// ---- aggregation layer1 (unnormalized): 64 threads per edge, float4 reduce ----
__global__ __launch_bounds__(256) void k_agg1(const int* __restrict__ src,
                                              const int* __restrict__ dst) {
    int t = threadIdx.x;
    int e = blockIdx.x * 4 + (t >> 6);
    if (e >= ET) return;
    int s, d;
    if (e < NE) { s = src[e]; d = dst[e]; }
    else        { s = d = e - NE; }
    int col = (t & 63) * 4;
    float w = g_e1[(long long)e * 4 + (col >> 6)];
    float4 hv = *(const float4*)(g_h1 + (long long)s * F1 + col);
    redAdd4(g_out1 + (long long)d * F1 + col,
            hv.x * w, hv.y * w, hv.z * w, hv.w * w);
}

// ---- GEMM2: g_h2 = relu(out1/s1 + b1) @ W2  (normalize+bias+relu fused) ----
__global__ __launch_bounds__(256) void k_gemm2(const float* __restrict__ W2,
                                               const float* __restrict__ b1) {
    __shared__ float As[16][64];
    __shared__ float Bs[16][64];
    int tid = threadIdx.x;
    int tx = tid & 15, ty = tid >> 4;
    int rowBase = blockIdx.x * 64;
    float acc[4][4];
#pragma unroll
    for (int i = 0; i < 4; i++)
#pragma unroll
        for (int j = 0; j < 4; j++) acc[i][j] = 0.f;

    for (int k0 = 0; k0 < 256; k0 += 16) {
        {
            int r = tid >> 2;
            int kk = (tid & 3) * 4;
            int grow = rowBase + r;
            float4 v = make_float4(0.f, 0.f, 0.f, 0.f);
            if (grow < NN) {
                int head = (k0 + kk) >> 6;   // constant within the float4
                float inv = 1.f / (g_s1[grow * 4 + head] + 1e-16f);
                float4 o = *(const float4*)(g_out1 + (long long)grow * F1 + k0 + kk);
                float4 bb = *(const float4*)(b1 + k0 + kk);
                v.x = fmaxf(fmaf(o.x, inv, bb.x), 0.f);
                v.y = fmaxf(fmaf(o.y, inv, bb.y), 0.f);
                v.z = fmaxf(fmaf(o.z, inv, bb.z), 0.f);
                v.w = fmaxf(fmaf(o.w, inv, bb.w), 0.f);
            }
            As[kk][r] = v.x; As[kk + 1][r] = v.y; As[kk + 2][r] = v.z; As[kk + 3][r] = v.w;
        }
        {
            int kk = tid >> 4, c = (tid & 15) * 4;
            *(float4*)&Bs[kk][c] = *(const float4*)(W2 + (k0 + kk) * 64 + c);
        }
        __syncthreads();
#pragma unroll
        for (int kk = 0; kk < 16; kk++) {
            float4 a = *(const float4*)&As[kk][ty * 4];
            float4 b = *(const float4*)&Bs[kk][tx * 4];
            float ra[4] = {a.x, a.y, a.z, a.w};
            float rb[4] = {b.x, b.y, b.z, b.w};
#pragma unroll
            for (int i = 0; i < 4; i++)
#pragma unroll
                for (int j = 0; j < 4; j++) acc[i][j] = fmaf(ra[i], rb[j], acc[i][j]);
        }
        __syncthreads();
    }
#pragma unroll
    for (int i = 0; i < 4; i++) {
        int row = rowBase + ty * 4 + i;
        if (row < NN)
            *(float4*)(g_h2 + (long long)row * 64 + tx * 4) =
                make_float4(acc[i][0], acc[i][1], acc[i][2], acc[i][3]);
    }
}

// ---- per-node attention dots layer2 (H=1): warp per node ----
__global__ void k_att2(const float* __restrict__ a_src, const float* __restrict__ a_dst) {
    int n = (blockIdx.x * blockDim.x + threadIdx.x) >> 5;
    int lane = threadIdx.x & 31;
    if (n >= NN) return;
    const float* hp = g_h2 + (long long)n * 64;
    float v0 = hp[lane], v1 = hp[lane + 32];
    float s = v0 * __ldg(a_src + lane) + v1 * __ldg(a_src + lane + 32);
    float d = v0 * __ldg(a_dst + lane) + v1 * __ldg(a_dst + lane + 32);
#pragma unroll
    for (int o = 16; o; o >>= 1) {
        s += __shfl_down_sync(0xFFFFFFFFu, s, o);
        d += __shfl_down_sync(0xFFFFFFFFu, d, o);
    }
    if (lane == 0) { g_als2[n] = s; g_ald2[n] = d; }
}

// ---- fused logit + exp + segment sum, layer2 ----
__global__ void k_edge_sum2(const int* __restrict__ src, const int* __restrict__ dst) {
    int e = blockIdx.x * blockDim.x + threadIdx.x;
    if (e >= ET) return;
    int s, d;
    if (e < NE) { s = src[e]; d = dst[e]; }
    else        { s = d = e - NE; }
    float x = expf(lrelu(g_als2[s] + g_ald2[d]));
    g_e2[e] = x;
    atomicAdd(&g_s2[d], x);
}

// ---- aggregation layer2 (unnormalized): 16 threads per edge ----
__global__ __launch_bounds__(256) void k_agg2(const int* __restrict__ src,
                                              const int* __restrict__ dst) {
    int t = threadIdx.x;
    int e = blockIdx.x * 16 + (t >> 4);
    if (e >= ET) return;
    int s, d;
    if (e < NE) { s = src[e]; d = dst[e]; }
    else        { s = d = e - NE; }
    int col = (t & 15) * 4;
    float w = g_e2[e];
    float4 hv = *(const float4*)(g_h2 + (long long)s * 64 + col);
    redAdd4(g_out2 + (long long)d * 64 + col,
            hv.x * w, hv.y * w, hv.z * w, hv.w * w);
}

// ---- epilogue layer2 (normalize+bias+relu) + mean pool: warp per node ----
__global__ void k_pool(const int* __restrict__ batch, const float* __restrict__ b2) {
    int n = (blockIdx.x * blockDim.x + threadIdx.x) >> 5;
    int lane = threadIdx.x & 31;
    if (n >= NN) return;
    int b = batch[n];
    float inv = 1.f / (g_s2[n] + 1e-16f);
    float v0 = fmaxf(fmaf(g_out2[(long long)n * 64 + lane],      inv, __ldg(b2 + lane)),      0.f);
    float v1 = fmaxf(fmaf(g_out2[(long long)n * 64 + lane + 32], inv, __ldg(b2 + lane + 32)), 0.f);
    atomicAdd(&g_pool[b * 64 + lane],      v0);
    atomicAdd(&g_pool[b * 64 + lane + 32], v1);
    if (lane == 0) atomicAdd(&g_cnt[b], 1.f);
}

// ---- final: out[64,2] = (pool/cnt) @ Wl + bl ----
__global__ void k_final(const float* __restrict__ Wl, const float* __restrict__ bl,
                        float* __restrict__ out) {
    int t = threadIdx.x;
    if (t >= NG * 2) return;
    int g = t >> 1, j = t & 1;
    float c = fmaxf(g_cnt[g], 1.f);
    float acc = 0.f;
#pragma unroll
    for (int k = 0; k < 64; k++) acc += (g_pool[g * 64 + k] / c) * Wl[k * 2 + j];
    out[g * 2 + j] = acc + bl[j];
}

extern "C" void kernel_launch(void* const* d_in, const int* in_sizes, int n_in,
                              void* d_out, int out_size) {
    const float* x     = (const float*)d_in[0];
    const int*   ei    = (const int*)d_in[1];      // int32 (JAX x64 disabled)
    const int*   batch = (const int*)d_in[2];
    const float* W1    = (const float*)d_in[3];
    const float* as1   = (const float*)d_in[4];
    const float* ad1   = (const float*)d_in[5];
    const float* b1    = (const float*)d_in[6];
    const float* W2    = (const float*)d_in[7];
    const float* as2   = (const float*)d_in[8];
    const float* ad2   = (const float*)d_in[9];
    const float* b2    = (const float*)d_in[10];
    const float* Wl    = (const float*)d_in[11];
    const float* bl    = (const float*)d_in[12];
    float*       out   = (float*)d_out;
    const int* src = ei;
    const int* dst = ei + NE;

    int eb = (ET + 255) / 256;

    k_init<<<4096, 256>>>();
    {
        dim3 g(2, (NN + 127) / 128);
        k_gemm1<<<g, 256>>>(x, W1);
    }
    k_att1<<<(NN * H1N + 7) / 8, 256>>>(as1, ad1);
    k_edge_sum1<<<eb, 256>>>(src, dst);
    k_agg1<<<(ET + 3) / 4, 256>>>(src, dst);
    k_gemm2<<<(NN + 63) / 64, 256>>>(W2, b1);
    k_att2<<<(NN + 7) / 8, 256>>>(as2, ad2);
    k_edge_sum2<<<eb, 256>>>(src, dst);
    k_agg2<<<(ET + 15) / 16, 256>>>(src, dst);
    k_pool<<<(NN + 7) / 8, 256>>>(batch, b2);
    k_final<<<1, 128>>>(Wl, bl, out);
}

// round 8
// speedup vs baseline: 1.4888x; 1.1554x over previous
#include <cuda_runtime.h>
#include <math.h>

#define NEG_SLOPE 0.2f
static const int NN  = 50000;   // nodes
static const int NE  = 800000;  // real edges
static const int ET  = 850000;  // edges + self loops
static const int NG  = 64;      // graphs
static const int FIN = 500;
static const int F1  = 256;     // H1*C1
static const int H1N = 4;
static const int C2  = 64;

// ---- scratch (static device allocations only, per harness rules) ----
__device__ __align__(16) float g_h1  [NN * F1];    // layer1 features h = x@W1
__device__ __align__(16) float g_out1[NN * F1];    // layer1 unnormalized aggregate
__device__ __align__(16) float g_h2  [NN * C2];    // layer2 features
__device__ __align__(16) float g_out2[NN * C2];    // layer2 unnormalized aggregate
__device__ __align__(16) float g_als1[NN * H1N];
__device__ __align__(16) float g_ald1[NN * H1N];
__device__ __align__(16) float g_s1  [NN * H1N];   // softmax denominators (unshifted)
__device__ __align__(16) float g_e1  [ET * H1N];   // exp(logits), unnormalized
__device__ float g_als2[NN];
__device__ float g_ald2[NN];
__device__ float g_s2  [NN];
__device__ float g_e2  [ET];
__device__ float g_pool[NG * C2];
__device__ float g_cnt [NG];

// ---- helpers ----
__device__ __forceinline__ void redAdd4(float* p, float a, float b, float c, float d) {
    asm volatile("red.global.add.v4.f32 [%0], {%1,%2,%3,%4};"
                 :: "l"(p), "f"(a), "f"(b), "f"(c), "f"(d) : "memory");
}
__device__ __forceinline__ float lrelu(float v) {
    return v > 0.f ? v : NEG_SLOPE * v;
}
__device__ __forceinline__ unsigned f2tf(float f) {
    unsigned u;
    asm("cvt.rna.tf32.f32 %0, %1;" : "=r"(u) : "f"(f));
    return u;
}
__device__ __forceinline__ void mma_tf32(float* c, const unsigned* a, const unsigned* b) {
    asm volatile(
        "mma.sync.aligned.m16n8k8.row.col.f32.tf32.tf32.f32 "
        "{%0,%1,%2,%3}, {%4,%5,%6,%7}, {%8,%9}, {%0,%1,%2,%3};\n"
        : "+f"(c[0]), "+f"(c[1]), "+f"(c[2]), "+f"(c[3])
        : "r"(a[0]), "r"(a[1]), "r"(a[2]), "r"(a[3]), "r"(b[0]), "r"(b[1]));
}

// ============================================================================
// GEMM1 (tf32 tensor cores): g_h1[50000,256] = X[50000,500] @ W1[500,256]
// 128x128 tile, BK=8 double-buffered, 8 warps each 32x64 (2x8 m16n8k8 tiles).
// Epilogue fuses: att1 src/dst dot products (each warp's 64 cols == one head),
// g_out1 zero-init, g_s1 zero-init.
// ============================================================================
__global__ __launch_bounds__(256) void k_gemm1(const float* __restrict__ X,
                                               const float* __restrict__ W,
                                               const float* __restrict__ a_src,
                                               const float* __restrict__ a_dst) {
    __shared__ unsigned As[2][128 * 8];   // [row][k], stride 8
    __shared__ unsigned Bs[2][128 * 9];   // [n][k], stride 9 (bank de-conflict)
    const int tid  = threadIdx.x;
    const int lane = tid & 31;
    const int wid  = tid >> 5;      // 0..7
    const int wm   = wid >> 1;      // 0..3 : warp row block (32 rows)
    const int wn   = wid & 1;       // 0..1 : warp col block (64 cols = one head)
    const int rowBase = blockIdx.y * 128;
    const int colBase = blockIdx.x * 128;
    const int r = lane >> 2, c = lane & 3;

    // global->shared mapping
    const int arow = tid >> 1, acoff = (tid & 1) * 4;   // A: 128 rows x 8 k
    const int brow = tid >> 5, bcol = (tid & 31) * 4;   // B: 8 k x 128 n

    float acc[2][8][4];
#pragma unroll
    for (int mt = 0; mt < 2; mt++)
#pragma unroll
        for (int nt = 0; nt < 8; nt++)
#pragma unroll
            for (int i = 0; i < 4; i++) acc[mt][nt][i] = 0.f;

    // ---- preload stage 0 ----
    {
        float4 va = make_float4(0.f, 0.f, 0.f, 0.f);
        int grow = rowBase + arow;
        if (grow < NN) va = *(const float4*)(X + (long long)grow * FIN + acoff);
        unsigned* ap = &As[0][arow * 8 + acoff];
        ap[0] = f2tf(va.x); ap[1] = f2tf(va.y); ap[2] = f2tf(va.z); ap[3] = f2tf(va.w);
        float4 vb = *(const float4*)(W + (long long)brow * F1 + colBase + bcol);
        Bs[0][(bcol + 0) * 9 + brow] = f2tf(vb.x);
        Bs[0][(bcol + 1) * 9 + brow] = f2tf(vb.y);
        Bs[0][(bcol + 2) * 9 + brow] = f2tf(vb.z);
        Bs[0][(bcol + 3) * 9 + brow] = f2tf(vb.w);
    }
    __syncthreads();

    // 63 k-stages of 8 (stage 62 half-padded with zeros: 500 = 62*8+4)
    for (int it = 0; it < 63; it++) {
        const int cur = it & 1, nxt = cur ^ 1;
        const bool pf = (it + 1 < 63);
        float4 va = make_float4(0.f, 0.f, 0.f, 0.f);
        float4 vb = make_float4(0.f, 0.f, 0.f, 0.f);
        bool aok = false, bok = false;
        if (pf) {
            int k0 = (it + 1) * 8;
            int grow = rowBase + arow;
            aok = (grow < NN) && (it + 1 < 62 || acoff == 0);
            if (aok) va = *(const float4*)(X + (long long)grow * FIN + k0 + acoff);
            bok = (it + 1 < 62) || (brow < 4);
            if (bok) vb = *(const float4*)(W + (long long)(k0 + brow) * F1 + colBase + bcol);
        }
        // compute on cur
        {
            const unsigned* as = As[cur];
            const unsigned* bs = Bs[cur];
            unsigned af[2][4];
#pragma unroll
            for (int mt = 0; mt < 2; mt++) {
                int rb = wm * 32 + mt * 16;
                af[mt][0] = as[(rb + r) * 8 + c];
                af[mt][1] = as[(rb + r + 8) * 8 + c];
                af[mt][2] = as[(rb + r) * 8 + c + 4];
                af[mt][3] = as[(rb + r + 8) * 8 + c + 4];
            }
#pragma unroll
            for (int nt = 0; nt < 8; nt++) {
                int nb = wn * 64 + nt * 8;
                unsigned bf[2];
                bf[0] = bs[(nb + r) * 9 + c];
                bf[1] = bs[(nb + r) * 9 + c + 4];
                mma_tf32(acc[0][nt], af[0], bf);
                mma_tf32(acc[1][nt], af[1], bf);
            }
        }
        if (pf) {
            unsigned* ap = &As[nxt][arow * 8 + acoff];
            ap[0] = f2tf(va.x); ap[1] = f2tf(va.y); ap[2] = f2tf(va.z); ap[3] = f2tf(va.w);
            Bs[nxt][(bcol + 0) * 9 + brow] = f2tf(vb.x);
            Bs[nxt][(bcol + 1) * 9 + brow] = f2tf(vb.y);
            Bs[nxt][(bcol + 2) * 9 + brow] = f2tf(vb.z);
            Bs[nxt][(bcol + 3) * 9 + brow] = f2tf(vb.w);
        }
        __syncthreads();
    }

    // ---- epilogue: store h1 tile + zero out1 tile ----
#pragma unroll
    for (int mt = 0; mt < 2; mt++)
#pragma unroll
        for (int hi = 0; hi < 2; hi++) {
            int row = rowBase + wm * 32 + mt * 16 + r + hi * 8;
            if (row < NN) {
#pragma unroll
                for (int nt = 0; nt < 8; nt++) {
                    int col = colBase + wn * 64 + nt * 8 + 2 * c;
                    float2 v = make_float2(acc[mt][nt][hi * 2], acc[mt][nt][hi * 2 + 1]);
                    *(float2*)(g_h1 + (long long)row * F1 + col) = v;
                    *(float2*)(g_out1 + (long long)row * F1 + col) = make_float2(0.f, 0.f);
                }
            }
        }

    // ---- fused att1 dots: this warp's 64 cols == head h ----
    const int h = blockIdx.x * 2 + wn;
#pragma unroll
    for (int mt = 0; mt < 2; mt++)
#pragma unroll
        for (int hi = 0; hi < 2; hi++) {
            float s = 0.f, d = 0.f;
#pragma unroll
            for (int nt = 0; nt < 8; nt++) {
                int col0 = nt * 8 + 2 * c;
                float v0 = acc[mt][nt][hi * 2], v1 = acc[mt][nt][hi * 2 + 1];
                s += v0 * __ldg(a_src + h * 64 + col0) + v1 * __ldg(a_src + h * 64 + col0 + 1);
                d += v0 * __ldg(a_dst + h * 64 + col0) + v1 * __ldg(a_dst + h * 64 + col0 + 1);
            }
            s += __shfl_xor_sync(0xFFFFFFFFu, s, 1);
            s += __shfl_xor_sync(0xFFFFFFFFu, s, 2);
            d += __shfl_xor_sync(0xFFFFFFFFu, d, 1);
            d += __shfl_xor_sync(0xFFFFFFFFu, d, 2);
            if ((lane & 3) == 0) {
                int row = rowBase + wm * 32 + mt * 16 + r + hi * 8;
                if (row < NN) {
                    g_als1[row * H1N + h] = s;
                    g_ald1[row * H1N + h] = d;
                    g_s1[row * H1N + h] = 0.f;
                }
            }
        }
}

// ---- fused logit + exp + segment sum, layer1 (shift-free softmax) ----
__global__ void k_edge_sum1(const int* __restrict__ src, const int* __restrict__ dst) {
    int e = blockIdx.x * blockDim.x + threadIdx.x;
    if (e >= ET) return;
    int s, d;
    if (e < NE) { s = src[e]; d = dst[e]; }
    else        { s = d = e - NE; }
    float4 as = *(const float4*)(g_als1 + s * 4);
    float4 ad = *(const float4*)(g_ald1 + d * 4);
    float x0 = expf(lrelu(as.x + ad.x));
    float x1 = expf(lrelu(as.y + ad.y));
    float x2 = expf(lrelu(as.z + ad.z));
    float x3 = expf(lrelu(as.w + ad.w));
    *(float4*)(g_e1 + (long long)e * 4) = make_float4(x0, x1, x2, x3);
    redAdd4(g_s1 + d * 4, x0, x1, x2, x3);
}

// ---- aggregation layer1 (unnormalized): 64 threads per edge ----
__global__ __launch_bounds__(256) void k_agg1(const int* __restrict__ src,
                                              const int* __restrict__ dst) {
    int t = threadIdx.x;
    int e = blockIdx.x * 4 + (t >> 6);
    if (e >= ET) return;
    int s, d;
    if (e < NE) { s = src[e]; d = dst[e]; }
    else        { s = d = e - NE; }
    int col = (t & 63) * 4;
    float w = g_e1[(long long)e * 4 + (col >> 6)];
    float4 hv = *(const float4*)(g_h1 + (long long)s * F1 + col);
    redAdd4(g_out1 + (long long)d * F1 + col,
            hv.x * w, hv.y * w, hv.z * w, hv.w * w);
}

// ============================================================================
// GEMM2: g_h2 = relu(out1/s1 + b1) @ W2 (normalize+bias+relu fused into A-load)
// Epilogue fuses: att2 dots, g_out2/g_s2 zero-init, g_pool/g_cnt zero (block 0).
// ============================================================================
__global__ __launch_bounds__(256) void k_gemm2(const float* __restrict__ W2,
                                               const float* __restrict__ b1,
                                               const float* __restrict__ a_src,
                                               const float* __restrict__ a_dst) {
    __shared__ float As[16][64];
    __shared__ float Bs[16][64];
    int tid = threadIdx.x;
    int tx = tid & 15, ty = tid >> 4;
    int rowBase = blockIdx.x * 64;
    float acc[4][4];
#pragma unroll
    for (int i = 0; i < 4; i++)
#pragma unroll
        for (int j = 0; j < 4; j++) acc[i][j] = 0.f;

    for (int k0 = 0; k0 < 256; k0 += 16) {
        {
            int rr = tid >> 2;
            int kk = (tid & 3) * 4;
            int grow = rowBase + rr;
            float4 v = make_float4(0.f, 0.f, 0.f, 0.f);
            if (grow < NN) {
                int head = (k0 + kk) >> 6;   // constant within the float4
                float inv = 1.f / (g_s1[grow * 4 + head] + 1e-16f);
                float4 o = *(const float4*)(g_out1 + (long long)grow * F1 + k0 + kk);
                float4 bb = *(const float4*)(b1 + k0 + kk);
                v.x = fmaxf(fmaf(o.x, inv, bb.x), 0.f);
                v.y = fmaxf(fmaf(o.y, inv, bb.y), 0.f);
                v.z = fmaxf(fmaf(o.z, inv, bb.z), 0.f);
                v.w = fmaxf(fmaf(o.w, inv, bb.w), 0.f);
            }
            As[kk][rr] = v.x; As[kk + 1][rr] = v.y; As[kk + 2][rr] = v.z; As[kk + 3][rr] = v.w;
        }
        {
            int kk = tid >> 4, cc = (tid & 15) * 4;
            *(float4*)&Bs[kk][cc] = *(const float4*)(W2 + (k0 + kk) * 64 + cc);
        }
        __syncthreads();
#pragma unroll
        for (int kk = 0; kk < 16; kk++) {
            float4 a = *(const float4*)&As[kk][ty * 4];
            float4 b = *(const float4*)&Bs[kk][tx * 4];
            float ra[4] = {a.x, a.y, a.z, a.w};
            float rb[4] = {b.x, b.y, b.z, b.w};
#pragma unroll
            for (int i = 0; i < 4; i++)
#pragma unroll
                for (int j = 0; j < 4; j++) acc[i][j] = fmaf(ra[i], rb[j], acc[i][j]);
        }
        __syncthreads();
    }
    // store h2 + zero out2
#pragma unroll
    for (int i = 0; i < 4; i++) {
        int row = rowBase + ty * 4 + i;
        if (row < NN) {
            *(float4*)(g_h2 + (long long)row * 64 + tx * 4) =
                make_float4(acc[i][0], acc[i][1], acc[i][2], acc[i][3]);
            *(float4*)(g_out2 + (long long)row * 64 + tx * 4) =
                make_float4(0.f, 0.f, 0.f, 0.f);
        }
    }
    // fused att2 dots: reduce over tx (16 lanes within each half-warp)
#pragma unroll
    for (int i = 0; i < 4; i++) {
        float s = 0.f, d = 0.f;
#pragma unroll
        for (int j = 0; j < 4; j++) {
            s += acc[i][j] * __ldg(a_src + tx * 4 + j);
            d += acc[i][j] * __ldg(a_dst + tx * 4 + j);
        }
#pragma unroll
        for (int o = 1; o < 16; o <<= 1) {
            s += __shfl_xor_sync(0xFFFFFFFFu, s, o);
            d += __shfl_xor_sync(0xFFFFFFFFu, d, o);
        }
        if (tx == 0) {
            int row = rowBase + ty * 4 + i;
            if (row < NN) { g_als2[row] = s; g_ald2[row] = d; g_s2[row] = 0.f; }
        }
    }
    // zero pool accumulators once
    if (blockIdx.x == 0) {
        for (int i = tid; i < NG * C2; i += 256) g_pool[i] = 0.f;
        if (tid < NG) g_cnt[tid] = 0.f;
    }
}

// ---- fused logit + exp + segment sum, layer2 ----
__global__ void k_edge_sum2(const int* __restrict__ src, const int* __restrict__ dst) {
    int e = blockIdx.x * blockDim.x + threadIdx.x;
    if (e >= ET) return;
    int s, d;
    if (e < NE) { s = src[e]; d = dst[e]; }
    else        { s = d = e - NE; }
    float x = expf(lrelu(g_als2[s] + g_ald2[d]));
    g_e2[e] = x;
    atomicAdd(&g_s2[d], x);
}

// ---- aggregation layer2 (unnormalized): 16 threads per edge ----
__global__ __launch_bounds__(256) void k_agg2(const int* __restrict__ src,
                                              const int* __restrict__ dst) {
    int t = threadIdx.x;
    int e = blockIdx.x * 16 + (t >> 4);
    if (e >= ET) return;
    int s, d;
    if (e < NE) { s = src[e]; d = dst[e]; }
    else        { s = d = e - NE; }
    int col = (t & 15) * 4;
    float w = g_e2[e];
    float4 hv = *(const float4*)(g_h2 + (long long)s * 64 + col);
    redAdd4(g_out2 + (long long)d * 64 + col,
            hv.x * w, hv.y * w, hv.z * w, hv.w * w);
}

// ---- epilogue layer2 (normalize+bias+relu) + mean pool: warp per node ----
__global__ void k_pool(const int* __restrict__ batch, const float* __restrict__ b2) {
    int n = (blockIdx.x * blockDim.x + threadIdx.x) >> 5;
    int lane = threadIdx.x & 31;
    if (n >= NN) return;
    int b = batch[n];
    float inv = 1.f / (g_s2[n] + 1e-16f);
    float v0 = fmaxf(fmaf(g_out2[(long long)n * 64 + lane],      inv, __ldg(b2 + lane)),      0.f);
    float v1 = fmaxf(fmaf(g_out2[(long long)n * 64 + lane + 32], inv, __ldg(b2 + lane + 32)), 0.f);
    atomicAdd(&g_pool[b * 64 + lane],      v0);
    atomicAdd(&g_pool[b * 64 + lane + 32], v1);
    if (lane == 0) atomicAdd(&g_cnt[b], 1.f);
}

// ---- final: out[64,2] = (pool/cnt) @ Wl + bl ----
__global__ void k_final(const float* __restrict__ Wl, const float* __restrict__ bl,
                        float* __restrict__ out) {
    int t = threadIdx.x;
    if (t >= NG * 2) return;
    int g = t >> 1, j = t & 1;
    float c = fmaxf(g_cnt[g], 1.f);
    float acc = 0.f;
#pragma unroll
    for (int k = 0; k < 64; k++) acc += (g_pool[g * 64 + k] / c) * Wl[k * 2 + j];
    out[g * 2 + j] = acc + bl[j];
}

extern "C" void kernel_launch(void* const* d_in, const int* in_sizes, int n_in,
                              void* d_out, int out_size) {
    const float* x     = (const float*)d_in[0];
    const int*   ei    = (const int*)d_in[1];      // int32 (JAX x64 disabled)
    const int*   batch = (const int*)d_in[2];
    const float* W1    = (const float*)d_in[3];
    const float* as1   = (const float*)d_in[4];
    const float* ad1   = (const float*)d_in[5];
    const float* b1    = (const float*)d_in[6];
    const float* W2    = (const float*)d_in[7];
    const float* as2   = (const float*)d_in[8];
    const float* ad2   = (const float*)d_in[9];
    const float* b2    = (const float*)d_in[10];
    const float* Wl    = (const float*)d_in[11];
    const float* bl    = (const float*)d_in[12];
    float*       out   = (float*)d_out;
    const int* src = ei;
    const int* dst = ei + NE;

    int eb = (ET + 255) / 256;

    {
        dim3 g(2, (NN + 127) / 128);
        k_gemm1<<<g, 256>>>(x, W1, as1, ad1);
    }
    k_edge_sum1<<<eb, 256>>>(src, dst);
    k_agg1<<<(ET + 3) / 4, 256>>>(src, dst);
    k_gemm2<<<(NN + 63) / 64, 256>>>(W2, b1, as2, ad2);
    k_edge_sum2<<<eb, 256>>>(src, dst);
    k_agg2<<<(ET + 15) / 16, 256>>>(src, dst);
    k_pool<<<(NN + 7) / 8, 256>>>(batch, b2);
    k_final<<<1, 128>>>(Wl, bl, out);
}

// round 10
// speedup vs baseline: 1.5016x; 1.0086x over previous
#include <cuda_runtime.h>
#include <math.h>

#define NEG_SLOPE 0.2f
static const int NN  = 50000;   // nodes
static const int NE  = 800000;  // real edges
static const int ET  = 850000;  // edges + self loops
static const int NG  = 64;      // graphs
static const int FIN = 500;
static const int F1  = 256;     // H1*C1
static const int H1N = 4;
static const int C2  = 64;

// ---- scratch (static device allocations only) ----
__device__ __align__(16) float g_h1  [NN * F1];
__device__ __align__(16) float g_out1[NN * F1];   // normalized aggregate, layer1
__device__ __align__(16) float g_h2  [NN * C2];
__device__ __align__(16) float g_out2[NN * C2];   // normalized aggregate, layer2
__device__ __align__(16) float g_als1[NN * H1N];
__device__ __align__(16) float g_ald1[NN * H1N];
__device__ __align__(16) float g_e1  [ET * H1N];  // exp(logits) layer1
__device__ float g_als2[NN];
__device__ float g_ald2[NN];
__device__ float g_e2  [ET];
__device__ float g_pool[NG * C2];
__device__ float g_cnt [NG];
// CSR by destination
__device__ int  g_deg[NN];
__device__ int  g_off[NN + 1];
__device__ int  g_cur[NN];
__device__ int2 g_csr[ET];     // (src, edge_id)

// ---- helpers ----
__device__ __forceinline__ float lrelu(float v) {
    return v > 0.f ? v : NEG_SLOPE * v;
}
__device__ __forceinline__ unsigned f2tf(float f) {
    unsigned u;
    asm("cvt.rna.tf32.f32 %0, %1;" : "=r"(u) : "f"(f));
    return u;
}
__device__ __forceinline__ void mma_tf32(float* c, const unsigned* a, const unsigned* b) {
    asm volatile(
        "mma.sync.aligned.m16n8k8.row.col.f32.tf32.tf32.f32 "
        "{%0,%1,%2,%3}, {%4,%5,%6,%7}, {%8,%9}, {%0,%1,%2,%3};\n"
        : "+f"(c[0]), "+f"(c[1]), "+f"(c[2]), "+f"(c[3])
        : "r"(a[0]), "r"(a[1]), "r"(a[2]), "r"(a[3]), "r"(b[0]), "r"(b[1]));
}

// ---- zero counters/accumulators that receive atomics ----
__global__ void k_zero() {
    int i = blockIdx.x * blockDim.x + threadIdx.x;
    if (i < NN) g_deg[i] = 0;
    if (i < NG * C2) g_pool[i] = 0.f;
    if (i < NG) g_cnt[i] = 0.f;
}

// ---- CSR build: histogram of destination degrees (self-loops included) ----
__global__ void k_hist(const int* __restrict__ dst) {
    int e = blockIdx.x * blockDim.x + threadIdx.x;
    if (e >= ET) return;
    int d = (e < NE) ? dst[e] : e - NE;
    atomicAdd(&g_deg[d], 1);
}

// ---- CSR build: exclusive prefix sum over 50000 degrees (1 block) ----
__global__ void k_scan() {
    __shared__ int ssum[1024];
    const int t = threadIdx.x;
    const int CH = (NN + 1023) / 1024;    // 49
    const int base = t * CH;
    int loc = 0;
    for (int i = 0; i < CH; i++) {
        int idx = base + i;
        if (idx < NN) loc += g_deg[idx];
    }
    ssum[t] = loc;
    __syncthreads();
    for (int o = 1; o < 1024; o <<= 1) {
        int v = (t >= o) ? ssum[t - o] : 0;
        __syncthreads();
        ssum[t] += v;
        __syncthreads();
    }
    int run = (t == 0) ? 0 : ssum[t - 1];
    for (int i = 0; i < CH; i++) {
        int idx = base + i;
        if (idx < NN) {
            g_off[idx] = run;
            g_cur[idx] = run;
            run += g_deg[idx];
        }
    }
    if (t == 0) g_off[NN] = ET;
}

// ============================================================================
// GEMM1 (tf32): g_h1[50000,256] = X[50000,500] @ W1[500,256]
// 128x128 tile, BK=8 double-buffered, 8 warps of 32x64. Fused att1 dots.
// ============================================================================
__global__ __launch_bounds__(256) void k_gemm1(const float* __restrict__ X,
                                               const float* __restrict__ W,
                                               const float* __restrict__ a_src,
                                               const float* __restrict__ a_dst) {
    __shared__ unsigned As[2][128 * 8];   // [row][k], stride 8
    __shared__ unsigned Bs[2][128 * 9];   // [n][k], stride 9
    const int tid  = threadIdx.x;
    const int lane = tid & 31;
    const int wid  = tid >> 5;
    const int wm   = wid >> 1;
    const int wn   = wid & 1;
    const int rowBase = blockIdx.y * 128;
    const int colBase = blockIdx.x * 128;
    const int r = lane >> 2, c = lane & 3;
    const int arow = tid >> 1, acoff = (tid & 1) * 4;
    const int brow = tid >> 5, bcol = (tid & 31) * 4;

    float acc[2][8][4];
#pragma unroll
    for (int mt = 0; mt < 2; mt++)
#pragma unroll
        for (int nt = 0; nt < 8; nt++)
#pragma unroll
            for (int i = 0; i < 4; i++) acc[mt][nt][i] = 0.f;

    {
        float4 va = make_float4(0.f, 0.f, 0.f, 0.f);
        int grow = rowBase + arow;
        if (grow < NN) va = *(const float4*)(X + (long long)grow * FIN + acoff);
        unsigned* ap = &As[0][arow * 8 + acoff];
        ap[0] = f2tf(va.x); ap[1] = f2tf(va.y); ap[2] = f2tf(va.z); ap[3] = f2tf(va.w);
        float4 vb = *(const float4*)(W + (long long)brow * F1 + colBase + bcol);
        Bs[0][(bcol + 0) * 9 + brow] = f2tf(vb.x);
        Bs[0][(bcol + 1) * 9 + brow] = f2tf(vb.y);
        Bs[0][(bcol + 2) * 9 + brow] = f2tf(vb.z);
        Bs[0][(bcol + 3) * 9 + brow] = f2tf(vb.w);
    }
    __syncthreads();

    for (int it = 0; it < 63; it++) {          // 500 = 62*8 + 4 (last stage zero-padded)
        const int cur = it & 1, nxt = cur ^ 1;
        const bool pf = (it + 1 < 63);
        float4 va = make_float4(0.f, 0.f, 0.f, 0.f);
        float4 vb = make_float4(0.f, 0.f, 0.f, 0.f);
        bool aok = false, bok = false;
        if (pf) {
            int k0 = (it + 1) * 8;
            int grow = rowBase + arow;
            aok = (grow < NN) && (it + 1 < 62 || acoff == 0);
            if (aok) va = *(const float4*)(X + (long long)grow * FIN + k0 + acoff);
            bok = (it + 1 < 62) || (brow < 4);
            if (bok) vb = *(const float4*)(W + (long long)(k0 + brow) * F1 + colBase + bcol);
        }
        {
            const unsigned* as = As[cur];
            const unsigned* bs = Bs[cur];
            unsigned af[2][4];
#pragma unroll
            for (int mt = 0; mt < 2; mt++) {
                int rb = wm * 32 + mt * 16;
                af[mt][0] = as[(rb + r) * 8 + c];
                af[mt][1] = as[(rb + r + 8) * 8 + c];
                af[mt][2] = as[(rb + r) * 8 + c + 4];
                af[mt][3] = as[(rb + r + 8) * 8 + c + 4];
            }
#pragma unroll
            for (int nt = 0; nt < 8; nt++) {
                int nb = wn * 64 + nt * 8;
                unsigned bf[2];
                bf[0] = bs[(nb + r) * 9 + c];
                bf[1] = bs[(nb + r) * 9 + c + 4];
                mma_tf32(acc[0][nt], af[0], bf);
                mma_tf32(acc[1][nt], af[1], bf);
            }
        }
        if (pf) {
            unsigned* ap = &As[nxt][arow * 8 + acoff];
            ap[0] = f2tf(va.x); ap[1] = f2tf(va.y); ap[2] = f2tf(va.z); ap[3] = f2tf(va.w);
            Bs[nxt][(bcol + 0) * 9 + brow] = f2tf(vb.x);
            Bs[nxt][(bcol + 1) * 9 + brow] = f2tf(vb.y);
            Bs[nxt][(bcol + 2) * 9 + brow] = f2tf(vb.z);
            Bs[nxt][(bcol + 3) * 9 + brow] = f2tf(vb.w);
        }
        __syncthreads();
    }

    // epilogue: store h1 tile
#pragma unroll
    for (int mt = 0; mt < 2; mt++)
#pragma unroll
        for (int hi = 0; hi < 2; hi++) {
            int row = rowBase + wm * 32 + mt * 16 + r + hi * 8;
            if (row < NN) {
#pragma unroll
                for (int nt = 0; nt < 8; nt++) {
                    int col = colBase + wn * 64 + nt * 8 + 2 * c;
                    *(float2*)(g_h1 + (long long)row * F1 + col) =
                        make_float2(acc[mt][nt][hi * 2], acc[mt][nt][hi * 2 + 1]);
                }
            }
        }
    // fused att1 dots (this warp's 64 cols == head h)
    const int h = blockIdx.x * 2 + wn;
#pragma unroll
    for (int mt = 0; mt < 2; mt++)
#pragma unroll
        for (int hi = 0; hi < 2; hi++) {
            float s = 0.f, d = 0.f;
#pragma unroll
            for (int nt = 0; nt < 8; nt++) {
                int col0 = nt * 8 + 2 * c;
                float v0 = acc[mt][nt][hi * 2], v1 = acc[mt][nt][hi * 2 + 1];
                s += v0 * __ldg(a_src + h * 64 + col0) + v1 * __ldg(a_src + h * 64 + col0 + 1);
                d += v0 * __ldg(a_dst + h * 64 + col0) + v1 * __ldg(a_dst + h * 64 + col0 + 1);
            }
            s += __shfl_xor_sync(0xFFFFFFFFu, s, 1);
            s += __shfl_xor_sync(0xFFFFFFFFu, s, 2);
            d += __shfl_xor_sync(0xFFFFFFFFu, d, 1);
            d += __shfl_xor_sync(0xFFFFFFFFu, d, 2);
            if ((lane & 3) == 0) {
                int row = rowBase + wm * 32 + mt * 16 + r + hi * 8;
                if (row < NN) {
                    g_als1[row * H1N + h] = s;
                    g_ald1[row * H1N + h] = d;
                }
            }
        }
}

// ---- CSR scatter + fused layer1 exp weights (shift-free softmax) ----
__global__ void k_scatter(const int* __restrict__ src, const int* __restrict__ dst) {
    int e = blockIdx.x * blockDim.x + threadIdx.x;
    if (e >= ET) return;
    int s, d;
    if (e < NE) { s = src[e]; d = dst[e]; }
    else        { s = d = e - NE; }
    float4 as = *(const float4*)(g_als1 + s * 4);
    float4 ad = *(const float4*)(g_ald1 + d * 4);
    *(float4*)(g_e1 + (long long)e * 4) =
        make_float4(expf(lrelu(as.x + ad.x)), expf(lrelu(as.y + ad.y)),
                    expf(lrelu(as.z + ad.z)), expf(lrelu(as.w + ad.w)));
    int pos = atomicAdd(&g_cur[d], 1);
    g_csr[pos] = make_int2(s, e);
}

// ---- layer1 aggregation via CSR gather (no atomics, normalized output) ----
__global__ __launch_bounds__(256) void k_agg1() {
    const int n = blockIdx.x;
    const int tid = threadIdx.x;
    const int h = tid >> 6;
    const int beg = g_off[n], end = g_off[n + 1];
    float acc = 0.f, wsum = 0.f;
    int j = beg;
    for (; j + 4 <= end; j += 4) {
        int2 c0 = g_csr[j], c1 = g_csr[j + 1], c2 = g_csr[j + 2], c3 = g_csr[j + 3];
        float w0 = g_e1[c0.y * 4 + h], w1 = g_e1[c1.y * 4 + h];
        float w2 = g_e1[c2.y * 4 + h], w3 = g_e1[c3.y * 4 + h];
        float v0 = g_h1[(long long)c0.x * F1 + tid];
        float v1 = g_h1[(long long)c1.x * F1 + tid];
        float v2 = g_h1[(long long)c2.x * F1 + tid];
        float v3 = g_h1[(long long)c3.x * F1 + tid];
        acc = fmaf(v0, w0, acc); acc = fmaf(v1, w1, acc);
        acc = fmaf(v2, w2, acc); acc = fmaf(v3, w3, acc);
        wsum += (w0 + w1) + (w2 + w3);
    }
    for (; j < end; j++) {
        int2 cc = g_csr[j];
        float w = g_e1[cc.y * 4 + h];
        float v = g_h1[(long long)cc.x * F1 + tid];
        acc = fmaf(v, w, acc);
        wsum += w;
    }
    g_out1[(long long)n * F1 + tid] = acc / (wsum + 1e-16f);
}

// ============================================================================
// GEMM2 (tf32): g_h2[50000,64] = relu(out1 + b1) @ W2[256,64]
// 128x64 tile, BK=8 double-buffered, 8 warps of 16x64. Fused att2 dots.
// ============================================================================
__global__ __launch_bounds__(256) void k_gemm2(const float* __restrict__ W2,
                                               const float* __restrict__ b1,
                                               const float* __restrict__ a_src,
                                               const float* __restrict__ a_dst) {
    __shared__ unsigned As[2][128 * 8];   // [row][k], stride 8
    __shared__ unsigned Bs[2][64 * 9];    // [n][k], stride 9
    const int tid  = threadIdx.x;
    const int lane = tid & 31;
    const int wid  = tid >> 5;            // warp owns rows wid*16..+15
    const int rowBase = blockIdx.x * 128;
    const int r = lane >> 2, c = lane & 3;
    const int arow = tid >> 1, acoff = (tid & 1) * 4;   // A: 128 rows x 8 k
    const int brow = tid >> 5, bcol = (tid & 31) * 2;   // B: 8 k x 64 n, float2

    float acc[8][4];
#pragma unroll
    for (int nt = 0; nt < 8; nt++)
#pragma unroll
        for (int i = 0; i < 4; i++) acc[nt][i] = 0.f;

    // preload stage 0
    {
        int grow = rowBase + arow;
        float4 v = make_float4(0.f, 0.f, 0.f, 0.f);
        if (grow < NN) {
            float4 o = *(const float4*)(g_out1 + (long long)grow * F1 + acoff);
            float4 bb = *(const float4*)(b1 + acoff);
            v.x = fmaxf(o.x + bb.x, 0.f); v.y = fmaxf(o.y + bb.y, 0.f);
            v.z = fmaxf(o.z + bb.z, 0.f); v.w = fmaxf(o.w + bb.w, 0.f);
        }
        unsigned* ap = &As[0][arow * 8 + acoff];
        ap[0] = f2tf(v.x); ap[1] = f2tf(v.y); ap[2] = f2tf(v.z); ap[3] = f2tf(v.w);
        float2 vb = *(const float2*)(W2 + (long long)brow * C2 + bcol);
        Bs[0][(bcol + 0) * 9 + brow] = f2tf(vb.x);
        Bs[0][(bcol + 1) * 9 + brow] = f2tf(vb.y);
    }
    __syncthreads();

    for (int it = 0; it < 32; it++) {         // K = 256 = 32*8
        const int cur = it & 1, nxt = cur ^ 1;
        const bool pf = (it + 1 < 32);
        float4 va = make_float4(0.f, 0.f, 0.f, 0.f);
        float2 vb = make_float2(0.f, 0.f);
        if (pf) {
            int k0 = (it + 1) * 8;
            int grow = rowBase + arow;
            if (grow < NN) {
                float4 o = *(const float4*)(g_out1 + (long long)grow * F1 + k0 + acoff);
                float4 bb = *(const float4*)(b1 + k0 + acoff);
                va.x = fmaxf(o.x + bb.x, 0.f); va.y = fmaxf(o.y + bb.y, 0.f);
                va.z = fmaxf(o.z + bb.z, 0.f); va.w = fmaxf(o.w + bb.w, 0.f);
            }
            vb = *(const float2*)(W2 + (long long)(k0 + brow) * C2 + bcol);
        }
        {
            const unsigned* as = As[cur];
            const unsigned* bs = Bs[cur];
            unsigned af[4];
            int rb = wid * 16;
            af[0] = as[(rb + r) * 8 + c];
            af[1] = as[(rb + r + 8) * 8 + c];
            af[2] = as[(rb + r) * 8 + c + 4];
            af[3] = as[(rb + r + 8) * 8 + c + 4];
#pragma unroll
            for (int nt = 0; nt < 8; nt++) {
                unsigned bf[2];
                bf[0] = bs[(nt * 8 + r) * 9 + c];
                bf[1] = bs[(nt * 8 + r) * 9 + c + 4];
                mma_tf32(acc[nt], af, bf);
            }
        }
        if (pf) {
            unsigned* ap = &As[nxt][arow * 8 + acoff];
            ap[0] = f2tf(va.x); ap[1] = f2tf(va.y); ap[2] = f2tf(va.z); ap[3] = f2tf(va.w);
            Bs[nxt][(bcol + 0) * 9 + brow] = f2tf(vb.x);
            Bs[nxt][(bcol + 1) * 9 + brow] = f2tf(vb.y);
        }
        __syncthreads();
    }

    // epilogue: store h2 + fused att2 dots
#pragma unroll
    for (int hi = 0; hi < 2; hi++) {
        int row = rowBase + wid * 16 + r + hi * 8;
        if (row < NN) {
#pragma unroll
            for (int nt = 0; nt < 8; nt++) {
                int col = nt * 8 + 2 * c;
                *(float2*)(g_h2 + (long long)row * C2 + col) =
                    make_float2(acc[nt][hi * 2], acc[nt][hi * 2 + 1]);
            }
        }
        float s = 0.f, d = 0.f;
#pragma unroll
        for (int nt = 0; nt < 8; nt++) {
            int col0 = nt * 8 + 2 * c;
            float v0 = acc[nt][hi * 2], v1 = acc[nt][hi * 2 + 1];
            s += v0 * __ldg(a_src + col0) + v1 * __ldg(a_src + col0 + 1);
            d += v0 * __ldg(a_dst + col0) + v1 * __ldg(a_dst + col0 + 1);
        }
        s += __shfl_xor_sync(0xFFFFFFFFu, s, 1);
        s += __shfl_xor_sync(0xFFFFFFFFu, s, 2);
        d += __shfl_xor_sync(0xFFFFFFFFu, d, 1);
        d += __shfl_xor_sync(0xFFFFFFFFu, d, 2);
        if ((lane & 3) == 0 && row < NN) { g_als2[row] = s; g_ald2[row] = d; }
    }
}

// ---- layer2 exp weights ----
__global__ void k_exp2(const int* __restrict__ src, const int* __restrict__ dst) {
    int e = blockIdx.x * blockDim.x + threadIdx.x;
    if (e >= ET) return;
    int s, d;
    if (e < NE) { s = src[e]; d = dst[e]; }
    else        { s = d = e - NE; }
    g_e2[e] = expf(lrelu(g_als2[s] + g_ald2[d]));
}

// ---- layer2 aggregation via CSR gather: 4 nodes per block ----
__global__ __launch_bounds__(256) void k_agg2() {
    const int tid = threadIdx.x;
    const int n = blockIdx.x * 4 + (tid >> 6);
    const int col = tid & 63;
    const int beg = g_off[n], end = g_off[n + 1];
    float acc = 0.f, wsum = 0.f;
    int j = beg;
    for (; j + 4 <= end; j += 4) {
        int2 c0 = g_csr[j], c1 = g_csr[j + 1], c2 = g_csr[j + 2], c3 = g_csr[j + 3];
        float w0 = g_e2[c0.y], w1 = g_e2[c1.y], w2 = g_e2[c2.y], w3 = g_e2[c3.y];
        float v0 = g_h2[(long long)c0.x * C2 + col];
        float v1 = g_h2[(long long)c1.x * C2 + col];
        float v2 = g_h2[(long long)c2.x * C2 + col];
        float v3 = g_h2[(long long)c3.x * C2 + col];
        acc = fmaf(v0, w0, acc); acc = fmaf(v1, w1, acc);
        acc = fmaf(v2, w2, acc); acc = fmaf(v3, w3, acc);
        wsum += (w0 + w1) + (w2 + w3);
    }
    for (; j < end; j++) {
        int2 cc = g_csr[j];
        float w = g_e2[cc.y];
        float v = g_h2[(long long)cc.x * C2 + col];
        acc = fmaf(v, w, acc);
        wsum += w;
    }
    g_out2[(long long)n * C2 + col] = acc / (wsum + 1e-16f);
}

// ---- layer2 epilogue (bias+relu) + mean pool: warp per node ----
__global__ void k_pool(const int* __restrict__ batch, const float* __restrict__ b2) {
    int n = (blockIdx.x * blockDim.x + threadIdx.x) >> 5;
    int lane = threadIdx.x & 31;
    if (n >= NN) return;
    int b = batch[n];
    float v0 = fmaxf(g_out2[(long long)n * 64 + lane]      + __ldg(b2 + lane),      0.f);
    float v1 = fmaxf(g_out2[(long long)n * 64 + lane + 32] + __ldg(b2 + lane + 32), 0.f);
    atomicAdd(&g_pool[b * 64 + lane],      v0);
    atomicAdd(&g_pool[b * 64 + lane + 32], v1);
    if (lane == 0) atomicAdd(&g_cnt[b], 1.f);
}

// ---- final: out[64,2] = (pool/cnt) @ Wl + bl ----
__global__ void k_final(const float* __restrict__ Wl, const float* __restrict__ bl,
                        float* __restrict__ out) {
    int t = threadIdx.x;
    if (t >= NG * 2) return;
    int g = t >> 1, j = t & 1;
    float c = fmaxf(g_cnt[g], 1.f);
    float acc = 0.f;
#pragma unroll
    for (int k = 0; k < 64; k++) acc += (g_pool[g * 64 + k] / c) * Wl[k * 2 + j];
    out[g * 2 + j] = acc + bl[j];
}

extern "C" void kernel_launch(void* const* d_in, const int* in_sizes, int n_in,
                              void* d_out, int out_size) {
    const float* x     = (const float*)d_in[0];
    const int*   ei    = (const int*)d_in[1];      // int32 (JAX x64 disabled)
    const int*   batch = (const int*)d_in[2];
    const float* W1    = (const float*)d_in[3];
    const float* as1   = (const float*)d_in[4];
    const float* ad1   = (const float*)d_in[5];
    const float* b1    = (const float*)d_in[6];
    const float* W2    = (const float*)d_in[7];
    const float* as2   = (const float*)d_in[8];
    const float* ad2   = (const float*)d_in[9];
    const float* b2    = (const float*)d_in[10];
    const float* Wl    = (const float*)d_in[11];
    const float* bl    = (const float*)d_in[12];
    float*       out   = (float*)d_out;
    const int* src = ei;
    const int* dst = ei + NE;

    int eb = (ET + 255) / 256;

    k_zero<<<(NN + 255) / 256, 256>>>();
    k_hist<<<eb, 256>>>(dst);
    k_scan<<<1, 1024>>>();
    {
        dim3 g(2, (NN + 127) / 128);
        k_gemm1<<<g, 256>>>(x, W1, as1, ad1);
    }
    k_scatter<<<eb, 256>>>(src, dst);
    k_agg1<<<NN, 256>>>();
    k_gemm2<<<(NN + 127) / 128, 256>>>(W2, b1, as2, ad2);
    k_exp2<<<eb, 256>>>(src, dst);
    k_agg2<<<NN / 4, 256>>>();
    k_pool<<<(NN + 7) / 8, 256>>>(batch, b2);
    k_final<<<1, 128>>>(Wl, bl, out);
}